// round 4
// baseline (speedup 1.0000x reference)
#include <cuda_runtime.h>
#include <cstdint>

typedef unsigned long long u64;

#define B_    256
#define T_    512
#define NPAIR 128

// ---- device scratch (no allocations allowed) ------------------------------
__device__ __align__(16) float  g_seqA[(size_t)T_ * B_ * 64];       // 33.5 MB [t][b][64]
__device__ __align__(16) u64    g_pre1[(size_t)T_ * NPAIR * 256];   // 134 MB  [t*128+pair][gate]
__device__ __align__(16) u64    g_pre2[(size_t)T_ * NPAIR * 256];   // 134 MB
__device__ __align__(16) float4 g_pb0[(size_t)T_ * B_];             // 2 MB    [t*256+b]

// ---- packed f32x2 helpers -------------------------------------------------
__device__ __forceinline__ u64 pk2(float a, float b) {
    u64 r; asm("mov.b64 %0, {%1, %2};" : "=l"(r) : "f"(a), "f"(b)); return r;
}
__device__ __forceinline__ void unpk(u64 v, float& a, float& b) {
    asm("mov.b64 {%0, %1}, %2;" : "=f"(a), "=f"(b) : "l"(v));
}
__device__ __forceinline__ u64 ffma2(u64 a, u64 b, u64 c) {
    u64 d; asm("fma.rn.f32x2 %0, %1, %2, %3;" : "=l"(d) : "l"(a), "l"(b), "l"(c)); return d;
}
__device__ __forceinline__ u64 add2(u64 a, u64 b) {
    u64 d; asm("add.rn.f32x2 %0, %1, %2;" : "=l"(d) : "l"(a), "l"(b)); return d;
}

// ---- fast activations (MUFU ex2+rcp, ~1e-7 err) ---------------------------
#define L2E 1.4426950408889634f
__device__ __forceinline__ float ex2a(float x) {
    float r; asm("ex2.approx.ftz.f32 %0, %1;" : "=f"(r) : "f"(x)); return r;
}
__device__ __forceinline__ float rcpa(float x) {
    float r; asm("rcp.approx.ftz.f32 %0, %1;" : "=f"(r) : "f"(x)); return r;
}
__device__ __forceinline__ float sga(float x) { return rcpa(1.f + ex2a(-L2E * x)); }
__device__ __forceinline__ float tna(float x) {
    return fmaf(-2.f, rcpa(1.f + ex2a(2.f * L2E * x)), 1.f);
}

// ---------------------------------------------------------------------------
// Fused H=64 LSTM recurrence (+ optional next-layer input projection).
// block = one batch pair, thread = one gate. Dim-packed weights (u64 pairs).
// MODE 0: Din=1 (layer a0), pre-gates inline from x. MODE 1: from presrc.
// INJ  1: also compute pregates of the NEXT layer on h(t) -> predst.
// WSEQ 1: write h sequence to g_seqA ([t][b][64]).
// ---------------------------------------------------------------------------
template <int MODE, int INJ, int WSEQ>
__global__ __launch_bounds__(256, 1) void recf(
    const float* __restrict__ w_hh,
    const float* __restrict__ xin,        // MODE0
    const float* __restrict__ w_ih,       // MODE0 (Din=1)
    const float* __restrict__ b_ih, const float* __restrict__ b_hh,
    const u64* __restrict__ presrc,       // MODE1
    const float* __restrict__ w_ih_n,     // INJ: [256][64]
    const float* __restrict__ b_ih_n, const float* __restrict__ b_hh_n,
    u64* __restrict__ predst)
{
    __shared__ __align__(16) float hb[2][64];
    __shared__ float2 gsm[256];
    __shared__ float  xs[2][T_];

    const int g = threadIdx.x;
    const int pair = blockIdx.x;

    // recurrent weights, dim-packed: (w[2j], w[2j+1]) as u64, 32 per row
    u64 whh2[32];
    {
        const u64* wr = reinterpret_cast<const u64*>(w_hh) + (size_t)g * 32;
#pragma unroll
        for (int j = 0; j < 32; ++j) whh2[j] = __ldg(wr + j);
    }
    u64 wih2[32];
    float biasN = 0.f;
    if (INJ) {
        const u64* wr = reinterpret_cast<const u64*>(w_ih_n) + (size_t)g * 32;
#pragma unroll
        for (int j = 0; j < 32; ++j) wih2[j] = __ldg(wr + j);
        biasN = __ldg(b_ih_n + g) + __ldg(b_hh_n + g);
    }

    float bias0 = 0.f, wih0 = 0.f;
    if (MODE == 0) {
        bias0 = __ldg(b_ih + g) + __ldg(b_hh + g);
        wih0  = __ldg(w_ih + g);
#pragma unroll
        for (int k = 0; k < 4; ++k) {
            int i = g + 256 * k, bl = i >> 9, t = i & 511;
            xs[bl][t] = xin[(size_t)(pair * 2 + bl) * T_ + t];
        }
    }
    if (g < 128) hb[g >> 6][g & 63] = 0.f;

    const bool istanh = (g >= 128 && g < 192);
    const float ca = istanh ? 2.f * L2E : -L2E;
    const float aa = istanh ? 1.f : 0.f;
    const float bm = istanh ? -2.f : 1.f;

    u64 pre0 = 0ull, pre1 = 0ull;
    if (MODE == 1) {
        pre0 = __ldg(presrc + (size_t)(0 * NPAIR + pair) * 256 + g);
        pre1 = __ldg(presrc + (size_t)(1 * NPAIR + pair) * 256 + g);
    }
    float c = 0.f;
    __syncthreads();

    for (int t = 0; t < T_; ++t) {
        // this layer's pregate scalars (for time t)
        float p0x, p1x;
        if (MODE == 0) {
            p0x = fmaf(wih0, xs[0][t], bias0);
            p1x = fmaf(wih0, xs[1][t], bias0);
        } else {
            unpk(pre0, p0x, p1x);
            pre0 = pre1;
            pre1 = (t + 2 < T_)
                 ? __ldg(presrc + (size_t)((t + 2) * NPAIR + pair) * 256 + g)
                 : 0ull;
        }

        // GEMVs over h(t-1), dim-packed, 4 (or 8) independent chains
        const ulonglong2* h0p = reinterpret_cast<const ulonglong2*>(hb[0]);
        const ulonglong2* h1p = reinterpret_cast<const ulonglong2*>(hb[1]);
        u64 A0 = 0ull, A1 = 0ull, Bu0 = 0ull, Bu1 = 0ull;
        u64 I0 = 0ull, I1 = 0ull, J0 = 0ull, J1 = 0ull;
#pragma unroll
        for (int j = 0; j < 16; ++j) {
            ulonglong2 q0 = h0p[j];
            ulonglong2 q1 = h1p[j];
            A0  = ffma2(whh2[2 * j + 0], q0.x, A0);
            A1  = ffma2(whh2[2 * j + 1], q0.y, A1);
            Bu0 = ffma2(whh2[2 * j + 0], q1.x, Bu0);
            Bu1 = ffma2(whh2[2 * j + 1], q1.y, Bu1);
            if (INJ) {
                I0 = ffma2(wih2[2 * j + 0], q0.x, I0);
                I1 = ffma2(wih2[2 * j + 1], q0.y, I1);
                J0 = ffma2(wih2[2 * j + 0], q1.x, J0);
                J1 = ffma2(wih2[2 * j + 1], q1.y, J1);
            }
        }
        // horizontal sums + this-layer activation
        u64 sA = add2(A0, A1), sB = add2(Bu0, Bu1);
        float ea, oa, eb, ob;
        unpk(sA, ea, oa); unpk(sB, eb, ob);
        float va = ea + oa + p0x;
        float vb = eb + ob + p1x;
        float ra = fmaf(bm, rcpa(1.f + ex2a(ca * va)), aa);
        float rb = fmaf(bm, rcpa(1.f + ex2a(ca * vb)), aa);
        gsm[g] = make_float2(ra, rb);

        // next-layer pregates computed on h(t-1) -> pregate index (t-1)
        if (INJ && t > 0) {
            u64 sI = add2(I0, I1), sJ = add2(J0, J1);
            float ei, oi, ej, oj;
            unpk(sI, ei, oi); unpk(sJ, ej, oj);
            predst[(size_t)((t - 1) * NPAIR + pair) * 256 + g] =
                pk2(ei + oi + biasN, ej + oj + biasN);
        }
        __syncthreads();

        if (g < 128) {
            int unit = g & 63, nb = g >> 6;
            float2 gi = gsm[unit], gf = gsm[unit + 64];
            float2 gg = gsm[unit + 128], go = gsm[unit + 192];
            float iv = nb ? gi.y : gi.x, fv = nb ? gf.y : gf.x;
            float gv = nb ? gg.y : gg.x, ov = nb ? go.y : go.x;
            c = fmaf(fv, c, iv * gv);
            float h = ov * tna(c);
            hb[nb][unit] = h;
            if (WSEQ)
                g_seqA[((size_t)t * B_ + pair * 2 + nb) * 64 + unit] = h;
        }
        __syncthreads();
    }

    // epilogue: pregates for t = T-1 from final h
    if (INJ) {
        const ulonglong2* h0p = reinterpret_cast<const ulonglong2*>(hb[0]);
        const ulonglong2* h1p = reinterpret_cast<const ulonglong2*>(hb[1]);
        u64 I0 = 0ull, I1 = 0ull, J0 = 0ull, J1 = 0ull;
#pragma unroll
        for (int j = 0; j < 16; ++j) {
            ulonglong2 q0 = h0p[j];
            ulonglong2 q1 = h1p[j];
            I0 = ffma2(wih2[2 * j + 0], q0.x, I0);
            I1 = ffma2(wih2[2 * j + 1], q0.y, I1);
            J0 = ffma2(wih2[2 * j + 0], q1.x, J0);
            J1 = ffma2(wih2[2 * j + 1], q1.y, J1);
        }
        u64 sI = add2(I0, I1), sJ = add2(J0, J1);
        float ei, oi, ej, oj;
        unpk(sI, ei, oi); unpk(sJ, ej, oj);
        predst[(size_t)((T_ - 1) * NPAIR + pair) * 256 + g] =
            pk2(ei + oi + biasN, ej + oj + biasN);
    }
}

// ---------------------------------------------------------------------------
// b0 pre-gates: g_pb0[t*256+b] = bias_b0 + W_ih_b0[4,64] . seqA[t][b]
// ---------------------------------------------------------------------------
__global__ __launch_bounds__(256, 1) void preb0(
    const float* __restrict__ w_ih, const float* __restrict__ b_ih,
    const float* __restrict__ b_hh)
{
    __shared__ u64 wsm[128];
    __shared__ float bsm[4];
    const int tid = threadIdx.x;
    if (tid < 128) wsm[tid] = __ldg(reinterpret_cast<const u64*>(w_ih) + tid);
    if (tid < 4) bsm[tid] = __ldg(b_ih + tid) + __ldg(b_hh + tid);
    __syncthreads();

    const size_t slot = (size_t)blockIdx.x * 256 + tid;  // = t*256 + b
    const u64* xp = reinterpret_cast<const u64*>(g_seqA) + slot * 32;
    u64 acc[4] = {0ull, 0ull, 0ull, 0ull};
#pragma unroll 8
    for (int j = 0; j < 32; ++j) {
        u64 xv = __ldg(xp + j);
#pragma unroll
        for (int gg = 0; gg < 4; ++gg)
            acc[gg] = ffma2(wsm[gg * 32 + j], xv, acc[gg]);
    }
    float r[4];
#pragma unroll
    for (int gg = 0; gg < 4; ++gg) {
        float e, o; unpk(acc[gg], e, o);
        r[gg] = e + o + bsm[gg];
    }
    g_pb0[slot] = make_float4(r[0], r[1], r[2], r[3]);
}

// ---------------------------------------------------------------------------
// b0,b1,b2 scalar recurrences, layer-pipelined. 8 blocks x 32 threads.
// ---------------------------------------------------------------------------
__device__ __forceinline__ void step1(float4 pre, float4 whh, float& c, float& h) {
    float iv = sga(fmaf(whh.x, h, pre.x));
    float fv = sga(fmaf(whh.y, h, pre.y));
    float gv = tna(fmaf(whh.z, h, pre.z));
    float ov = sga(fmaf(whh.w, h, pre.w));
    c = fmaf(fv, c, iv * gv);
    h = ov * tna(c);
}

__global__ __launch_bounds__(32, 1) void b012(
    const float* __restrict__ whh0,
    const float* __restrict__ wih1, const float* __restrict__ whh1,
    const float* __restrict__ bih1, const float* __restrict__ bhh1,
    const float* __restrict__ wih2, const float* __restrict__ whh2,
    const float* __restrict__ bih2, const float* __restrict__ bhh2,
    float* __restrict__ out)
{
    const int b = blockIdx.x * 32 + threadIdx.x;
    float4 W0 = make_float4(whh0[0], whh0[1], whh0[2], whh0[3]);
    float4 I1 = make_float4(wih1[0], wih1[1], wih1[2], wih1[3]);
    float4 H1 = make_float4(whh1[0], whh1[1], whh1[2], whh1[3]);
    float4 B1 = make_float4(bih1[0] + bhh1[0], bih1[1] + bhh1[1],
                            bih1[2] + bhh1[2], bih1[3] + bhh1[3]);
    float4 I2 = make_float4(wih2[0], wih2[1], wih2[2], wih2[3]);
    float4 H2 = make_float4(whh2[0], whh2[1], whh2[2], whh2[3]);
    float4 B2 = make_float4(bih2[0] + bhh2[0], bih2[1] + bhh2[1],
                            bih2[2] + bhh2[2], bih2[3] + bhh2[3]);

    float c0 = 0.f, h0 = 0.f, c1 = 0.f, h1 = 0.f, c2 = 0.f, h2v = 0.f;
    float4 p0 = g_pb0[b];
    float4 p1 = g_pb0[256 + b];

    for (int tt = 0; tt < T_ + 2; ++tt) {
        float4 pn = (tt + 2 < T_) ? g_pb0[(size_t)(tt + 2) * 256 + b]
                                  : make_float4(0.f, 0.f, 0.f, 0.f);
        float in0 = h0, in1 = h1;
        if (tt < T_) step1(p0, W0, c0, h0);
        if (tt >= 1 && tt < T_ + 1) {
            float4 pre = make_float4(fmaf(I1.x, in0, B1.x), fmaf(I1.y, in0, B1.y),
                                     fmaf(I1.z, in0, B1.z), fmaf(I1.w, in0, B1.w));
            step1(pre, H1, c1, h1);
        }
        if (tt >= 2) {
            float4 pre = make_float4(fmaf(I2.x, in1, B2.x), fmaf(I2.y, in1, B2.y),
                                     fmaf(I2.z, in1, B2.z), fmaf(I2.w, in1, B2.w));
            step1(pre, H2, c2, h2v);
            out[(size_t)b * T_ + (tt - 2)] = h2v;
        }
        p0 = p1; p1 = pn;
    }
}

// ---------------------------------------------------------------------------
extern "C" void kernel_launch(void* const* d_in, const int* in_sizes, int n_in,
                              void* d_out, int out_size)
{
    const float* x = (const float*)d_in[0];
    const float *wih_a0 = (const float*)d_in[1],  *whh_a0 = (const float*)d_in[2];
    const float *bih_a0 = (const float*)d_in[3],  *bhh_a0 = (const float*)d_in[4];
    const float *wih_a1 = (const float*)d_in[5],  *whh_a1 = (const float*)d_in[6];
    const float *bih_a1 = (const float*)d_in[7],  *bhh_a1 = (const float*)d_in[8];
    const float *wih_a2 = (const float*)d_in[9],  *whh_a2 = (const float*)d_in[10];
    const float *bih_a2 = (const float*)d_in[11], *bhh_a2 = (const float*)d_in[12];
    const float *wih_b0 = (const float*)d_in[13], *whh_b0 = (const float*)d_in[14];
    const float *bih_b0 = (const float*)d_in[15], *bhh_b0 = (const float*)d_in[16];
    const float *wih_b1 = (const float*)d_in[17], *whh_b1 = (const float*)d_in[18];
    const float *bih_b1 = (const float*)d_in[19], *bhh_b1 = (const float*)d_in[20];
    const float *wih_b2 = (const float*)d_in[21], *whh_b2 = (const float*)d_in[22];
    const float *bih_b2 = (const float*)d_in[23], *bhh_b2 = (const float*)d_in[24];
    float* out = (float*)d_out;

    // a0 recurrence + fused a1 input projection -> g_pre1
    recf<0, 1, 0><<<NPAIR, 256>>>(whh_a0, x, wih_a0, bih_a0, bhh_a0,
                                  nullptr, wih_a1, bih_a1, bhh_a1, g_pre1);
    // a1 recurrence (from g_pre1) + fused a2 input projection -> g_pre2
    recf<1, 1, 0><<<NPAIR, 256>>>(whh_a1, nullptr, nullptr, nullptr, nullptr,
                                  g_pre1, wih_a2, bih_a2, bhh_a2, g_pre2);
    // a2 recurrence (from g_pre2), writes h sequence -> g_seqA
    recf<1, 0, 1><<<NPAIR, 256>>>(whh_a2, nullptr, nullptr, nullptr, nullptr,
                                  g_pre2, nullptr, nullptr, nullptr, nullptr);
    // b0 pre-gates from g_seqA
    preb0<<<512, 256>>>(wih_b0, bih_b0, bhh_b0);
    // b0/b1/b2 fused scalar recurrences -> out
    b012<<<8, 32>>>(whh_b0, wih_b1, whh_b1, bih_b1, bhh_b1,
                    wih_b2, whh_b2, bih_b2, bhh_b2, out);
}

// round 5
// speedup vs baseline: 2.0540x; 2.0540x over previous
#include <cuda_runtime.h>
#include <cstdint>

typedef unsigned long long u64;

#define B_    256
#define T_    512
#define NPAIR 128

// ---- device scratch (no allocations allowed) ------------------------------
__device__ __align__(16) float  g_seqA[(size_t)T_ * B_ * 64];      // 33.5 MB [t][b][64]
__device__ __align__(16) float  g_seqB[(size_t)T_ * B_ * 64];      // 33.5 MB
__device__ __align__(16) u64    g_prebuf[(size_t)T_ * NPAIR * 256];// 134 MB [t*128+pair][gate] -> (b0,b1)
__device__ __align__(16) float4 g_pb0[(size_t)T_ * B_];            // 2 MB   [t*256+b]

// ---- packed f32x2 helpers -------------------------------------------------
__device__ __forceinline__ u64 pk2(float a, float b) {
    u64 r; asm("mov.b64 %0, {%1, %2};" : "=l"(r) : "f"(a), "f"(b)); return r;
}
__device__ __forceinline__ void unpk(u64 v, float& a, float& b) {
    asm("mov.b64 {%0, %1}, %2;" : "=f"(a), "=f"(b) : "l"(v));
}
__device__ __forceinline__ u64 ffma2(u64 a, u64 b, u64 c) {
    u64 d; asm("fma.rn.f32x2 %0, %1, %2, %3;" : "=l"(d) : "l"(a), "l"(b), "l"(c)); return d;
}
__device__ __forceinline__ u64 add2(u64 a, u64 b) {
    u64 d; asm("add.rn.f32x2 %0, %1, %2;" : "=l"(d) : "l"(a), "l"(b)); return d;
}

// ---- fast activations (MUFU ex2+rcp, ~1e-7 err) ---------------------------
#define L2E 1.4426950408889634f
__device__ __forceinline__ float ex2a(float x) {
    float r; asm("ex2.approx.ftz.f32 %0, %1;" : "=f"(r) : "f"(x)); return r;
}
__device__ __forceinline__ float rcpa(float x) {
    float r; asm("rcp.approx.ftz.f32 %0, %1;" : "=f"(r) : "f"(x)); return r;
}
__device__ __forceinline__ float sga(float x) { return rcpa(1.f + ex2a(-L2E * x)); }
__device__ __forceinline__ float tna(float x) {
    return fmaf(-2.f, rcpa(1.f + ex2a(2.f * L2E * x)), 1.f);
}

// ---------------------------------------------------------------------------
// H=64 LSTM recurrence, gate-paired via shfl, ONE barrier per step.
// block = one batch pair, 256 threads.
//   warp w (0..7): nb = w>>2, units (w&3)*16 + (lane&15), role = lane>>4
//   role0 owns gates (i: u, g: u+128); role1 owns (f: u+64, o: u+192)
//   role0 sends P = sigma(i)*tanh(g) to role1 via shfl_xor(16);
//   role1 updates c,h and writes h to double-buffered smem.
// MODE 0: Din=1 (layer a0), pre-gates inline from x. MODE 1: from g_prebuf.
// Writes h sequence [t][b][64] to g_seqA (outsel=0) or g_seqB (outsel=1).
// ---------------------------------------------------------------------------
template <int MODE>
__global__ __launch_bounds__(256, 1) void rec64(
    const float* __restrict__ w_hh, const float* __restrict__ xin,
    const float* __restrict__ w_ih, const float* __restrict__ b_ih,
    const float* __restrict__ b_hh, int outsel)
{
    __shared__ __align__(16) float hsm[2][2][64];   // [phase][batch][unit]
    __shared__ float xs[2][T_];

    const int tid  = threadIdx.x;
    const int lane = tid & 31, warp = tid >> 5;
    const int nb   = warp >> 2;
    const int u    = (warp & 3) * 16 + (lane & 15);
    const int role = lane >> 4;                     // 0: (i,g)  1: (f,o)
    const int pair = blockIdx.x;
    float* outf = outsel ? g_seqB : g_seqA;

    const int gate0 = u + (role ? 64 : 0);          // i or f (always sigmoid)
    const int gate1 = u + (role ? 192 : 128);       // g (tanh) or o (sigmoid)

    // dim-packed weight rows: 2 gates x 32 u64 = 128 regs
    u64 wA[32], wB[32];
    {
        const u64* wr0 = reinterpret_cast<const u64*>(w_hh) + (size_t)gate0 * 32;
        const u64* wr1 = reinterpret_cast<const u64*>(w_hh) + (size_t)gate1 * 32;
#pragma unroll
        for (int j = 0; j < 32; ++j) { wA[j] = __ldg(wr0 + j); wB[j] = __ldg(wr1 + j); }
    }

    float biasA = 0.f, biasB = 0.f, wiA = 0.f, wiB = 0.f;
    if (MODE == 0) {
        biasA = __ldg(b_ih + gate0) + __ldg(b_hh + gate0);
        biasB = __ldg(b_ih + gate1) + __ldg(b_hh + gate1);
        wiA   = __ldg(w_ih + gate0);
        wiB   = __ldg(w_ih + gate1);
#pragma unroll
        for (int k = 0; k < 4; ++k) {
            int i = tid + 256 * k, bl = i >> 9, t = i & 511;
            xs[bl][t] = xin[(size_t)(pair * 2 + bl) * T_ + t];
        }
    }
    if (tid < 128) {
        hsm[0][tid >> 6][tid & 63] = 0.f;
        hsm[1][tid >> 6][tid & 63] = 0.f;
    }

    // vB activation constants: role0 -> tanh, role1 -> sigmoid
    const float caB = role ? -L2E : 2.f * L2E;
    const float aaB = role ? 0.f : 1.f;
    const float bmB = role ? 1.f : -2.f;

    // MODE1 pregate prefetch (scalar floats, depth 2)
    const float* pf = reinterpret_cast<const float*>(g_prebuf);
    const size_t strideT = (size_t)NPAIR * 256 * 2;   // floats per t
    float pA0 = 0.f, pB0 = 0.f, pA1 = 0.f, pB1 = 0.f;
    const float* pfA = nullptr; const float* pfB = nullptr;
    if (MODE == 1) {
        size_t baseA = ((size_t)pair * 256 + gate0) * 2 + nb;
        size_t baseB = ((size_t)pair * 256 + gate1) * 2 + nb;
        pA0 = __ldg(pf + baseA);
        pB0 = __ldg(pf + baseB);
        pA1 = __ldg(pf + baseA + strideT);
        pB1 = __ldg(pf + baseB + strideT);
        pfA = pf + baseA + 2 * strideT;
        pfB = pf + baseB + 2 * strideT;
    }

    float c = 0.f;
    __syncthreads();
    int p = 0;

    for (int t = 0; t < T_; ++t) {
        float pA, pB;
        if (MODE == 0) {
            float xv = xs[nb][t];
            pA = fmaf(wiA, xv, biasA);
            pB = fmaf(wiB, xv, biasB);
        } else {
            pA = pA0; pB = pB0;
            pA0 = pA1; pB0 = pB1;
            if (t + 2 < T_) {
                pA1 = __ldg(pfA); pB1 = __ldg(pfB);
                pfA += strideT;   pfB += strideT;
            }
        }

        const ulonglong2* hp = reinterpret_cast<const ulonglong2*>(hsm[p][nb]);
        u64 a0 = 0ull, a1 = 0ull, b0 = 0ull, b1 = 0ull;
#pragma unroll
        for (int j = 0; j < 16; ++j) {
            ulonglong2 q = hp[j];
            a0 = ffma2(wA[2 * j + 0], q.x, a0);
            a1 = ffma2(wA[2 * j + 1], q.y, a1);
            b0 = ffma2(wB[2 * j + 0], q.x, b0);
            b1 = ffma2(wB[2 * j + 1], q.y, b1);
        }
        float eA, oA, eB, oB;
        unpk(add2(a0, a1), eA, oA);
        unpk(add2(b0, b1), eB, oB);
        float vA = eA + oA + pA;
        float vB = eB + oB + pB;

        float sA = sga(vA);                                    // i (role0) / f (role1)
        float sB = fmaf(bmB, rcpa(1.f + ex2a(caB * vB)), aaB); // g / o
        float P  = sA * sB;                                    // role0: i*g
        float Px = __shfl_xor_sync(0xffffffffu, P, 16);

        float cn = fmaf(sA, c, Px);      // role1: f*c + i*g
        float hn = sB * tna(cn);         // role1: o*tanh(c)
        if (role) {
            c = cn;
            hsm[p ^ 1][nb][u] = hn;
            outf[((size_t)t * B_ + pair * 2 + nb) * 64 + u] = hn;
        }
        __syncthreads();
        p ^= 1;
    }
}

// ---------------------------------------------------------------------------
// Input projection GEMM (dim-packed weights): for pair-slot s,
//   prebuf[s][g] = ( bias + w_ih[g].x[t][2p],  bias + w_ih[g].x[t][2p+1] )
// 1024 blocks x 256 threads, 2 blocks/SM. 64 pair-slots/block, smem dbl-buf.
// ---------------------------------------------------------------------------
__global__ __launch_bounds__(256, 2) void inj64(
    int insel, const float* __restrict__ w_ih,
    const float* __restrict__ b_ih, const float* __restrict__ b_hh)
{
    __shared__ __align__(16) float xsm[2][8 * 128];   // 8 KB
    const float* xseq = insel ? g_seqB : g_seqA;
    const int g = threadIdx.x;

    u64 w2[32];
    const u64* wrow = reinterpret_cast<const u64*>(w_ih) + (size_t)g * 32;
#pragma unroll
    for (int j = 0; j < 32; ++j) w2[j] = __ldg(wrow + j);
    const float bb = __ldg(b_ih + g) + __ldg(b_hh + g);

    const size_t s0 = (size_t)blockIdx.x * 64;
    const float4* src = reinterpret_cast<const float4*>(xseq) + s0 * 32;

    {
        float4 v = __ldg(src + g);
        reinterpret_cast<float4*>(xsm[0])[g] = v;
    }
    __syncthreads();

    for (int tl = 0; tl < 8; ++tl) {
        const int buf = tl & 1;
        float4 nxt;
        if (tl + 1 < 8) nxt = __ldg(src + (size_t)(tl + 1) * 256 + g);

#pragma unroll 2
        for (int sl = 0; sl < 8; ++sl) {
            const ulonglong2* x0 = reinterpret_cast<const ulonglong2*>(xsm[buf] + sl * 128);
            const ulonglong2* x1 = x0 + 16;
            u64 a0 = 0ull, a1 = 0ull, c0 = 0ull, c1 = 0ull;
#pragma unroll
            for (int j = 0; j < 16; ++j) {
                ulonglong2 q0 = x0[j];
                ulonglong2 q1 = x1[j];
                a0 = ffma2(w2[2 * j + 0], q0.x, a0);
                a1 = ffma2(w2[2 * j + 1], q0.y, a1);
                c0 = ffma2(w2[2 * j + 0], q1.x, c0);
                c1 = ffma2(w2[2 * j + 1], q1.y, c1);
            }
            u64 sa = add2(a0, a1), sc = add2(c0, c1);
            float ea, oa, ec, oc;
            unpk(sa, ea, oa); unpk(sc, ec, oc);
            g_prebuf[(s0 + (size_t)tl * 8 + sl) * 256 + g] = pk2(ea + oa + bb, ec + oc + bb);
        }

        if (tl + 1 < 8) {
            reinterpret_cast<float4*>(xsm[buf ^ 1])[g] = nxt;
            __syncthreads();
        }
    }
}

// ---------------------------------------------------------------------------
// b0 pre-gates: g_pb0[t*256+b] = bias_b0 + W_ih_b0[4,64] . seqA[t][b]
// ---------------------------------------------------------------------------
__global__ __launch_bounds__(256, 1) void preb0(
    const float* __restrict__ w_ih, const float* __restrict__ b_ih,
    const float* __restrict__ b_hh)
{
    __shared__ u64 wsm[128];
    __shared__ float bsm[4];
    const int tid = threadIdx.x;
    if (tid < 128) wsm[tid] = __ldg(reinterpret_cast<const u64*>(w_ih) + tid);
    if (tid < 4) bsm[tid] = __ldg(b_ih + tid) + __ldg(b_hh + tid);
    __syncthreads();

    const size_t slot = (size_t)blockIdx.x * 256 + tid;  // = t*256 + b
    const u64* xp = reinterpret_cast<const u64*>(g_seqA) + slot * 32;
    u64 acc[4] = {0ull, 0ull, 0ull, 0ull};
#pragma unroll 8
    for (int j = 0; j < 32; ++j) {
        u64 xv = __ldg(xp + j);
#pragma unroll
        for (int gg = 0; gg < 4; ++gg)
            acc[gg] = ffma2(wsm[gg * 32 + j], xv, acc[gg]);
    }
    float r[4];
#pragma unroll
    for (int gg = 0; gg < 4; ++gg) {
        float e, o; unpk(acc[gg], e, o);
        r[gg] = e + o + bsm[gg];
    }
    g_pb0[slot] = make_float4(r[0], r[1], r[2], r[3]);
}

// ---------------------------------------------------------------------------
// b0,b1,b2 scalar recurrences, layer-pipelined. 8 blocks x 32 threads.
// ---------------------------------------------------------------------------
__device__ __forceinline__ void step1(float4 pre, float4 whh, float& c, float& h) {
    float iv = sga(fmaf(whh.x, h, pre.x));
    float fv = sga(fmaf(whh.y, h, pre.y));
    float gv = tna(fmaf(whh.z, h, pre.z));
    float ov = sga(fmaf(whh.w, h, pre.w));
    c = fmaf(fv, c, iv * gv);
    h = ov * tna(c);
}

__global__ __launch_bounds__(32, 1) void b012(
    const float* __restrict__ whh0,
    const float* __restrict__ wih1, const float* __restrict__ whh1,
    const float* __restrict__ bih1, const float* __restrict__ bhh1,
    const float* __restrict__ wih2, const float* __restrict__ whh2,
    const float* __restrict__ bih2, const float* __restrict__ bhh2,
    float* __restrict__ out)
{
    const int b = blockIdx.x * 32 + threadIdx.x;
    float4 W0 = make_float4(whh0[0], whh0[1], whh0[2], whh0[3]);
    float4 I1 = make_float4(wih1[0], wih1[1], wih1[2], wih1[3]);
    float4 H1 = make_float4(whh1[0], whh1[1], whh1[2], whh1[3]);
    float4 B1 = make_float4(bih1[0] + bhh1[0], bih1[1] + bhh1[1],
                            bih1[2] + bhh1[2], bih1[3] + bhh1[3]);
    float4 I2 = make_float4(wih2[0], wih2[1], wih2[2], wih2[3]);
    float4 H2 = make_float4(whh2[0], whh2[1], whh2[2], whh2[3]);
    float4 B2 = make_float4(bih2[0] + bhh2[0], bih2[1] + bhh2[1],
                            bih2[2] + bhh2[2], bih2[3] + bhh2[3]);

    float c0 = 0.f, h0 = 0.f, c1 = 0.f, h1 = 0.f, c2 = 0.f, h2v = 0.f;
    float4 p0 = g_pb0[b];
    float4 p1 = g_pb0[256 + b];

    for (int tt = 0; tt < T_ + 2; ++tt) {
        float4 pn = (tt + 2 < T_) ? g_pb0[(size_t)(tt + 2) * 256 + b]
                                  : make_float4(0.f, 0.f, 0.f, 0.f);
        float in0 = h0, in1 = h1;
        if (tt < T_) step1(p0, W0, c0, h0);
        if (tt >= 1 && tt < T_ + 1) {
            float4 pre = make_float4(fmaf(I1.x, in0, B1.x), fmaf(I1.y, in0, B1.y),
                                     fmaf(I1.z, in0, B1.z), fmaf(I1.w, in0, B1.w));
            step1(pre, H1, c1, h1);
        }
        if (tt >= 2) {
            float4 pre = make_float4(fmaf(I2.x, in1, B2.x), fmaf(I2.y, in1, B2.y),
                                     fmaf(I2.z, in1, B2.z), fmaf(I2.w, in1, B2.w));
            step1(pre, H2, c2, h2v);
            out[(size_t)b * T_ + (tt - 2)] = h2v;
        }
        p0 = p1; p1 = pn;
    }
}

// ---------------------------------------------------------------------------
extern "C" void kernel_launch(void* const* d_in, const int* in_sizes, int n_in,
                              void* d_out, int out_size)
{
    const float* x = (const float*)d_in[0];
    const float *wih_a0 = (const float*)d_in[1],  *whh_a0 = (const float*)d_in[2];
    const float *bih_a0 = (const float*)d_in[3],  *bhh_a0 = (const float*)d_in[4];
    const float *wih_a1 = (const float*)d_in[5],  *whh_a1 = (const float*)d_in[6];
    const float *bih_a1 = (const float*)d_in[7],  *bhh_a1 = (const float*)d_in[8];
    const float *wih_a2 = (const float*)d_in[9],  *whh_a2 = (const float*)d_in[10];
    const float *bih_a2 = (const float*)d_in[11], *bhh_a2 = (const float*)d_in[12];
    const float *wih_b0 = (const float*)d_in[13], *whh_b0 = (const float*)d_in[14];
    const float *bih_b0 = (const float*)d_in[15], *bhh_b0 = (const float*)d_in[16];
    const float *wih_b1 = (const float*)d_in[17], *whh_b1 = (const float*)d_in[18];
    const float *bih_b1 = (const float*)d_in[19], *bhh_b1 = (const float*)d_in[20];
    const float *wih_b2 = (const float*)d_in[21], *whh_b2 = (const float*)d_in[22];
    const float *bih_b2 = (const float*)d_in[23], *bhh_b2 = (const float*)d_in[24];
    float* out = (float*)d_out;

    // a0: Din=1 recurrence -> seqA
    rec64<0><<<NPAIR, 256>>>(whh_a0, x, wih_a0, bih_a0, bhh_a0, 0);
    // a1: inj from seqA -> prebuf; recurrence -> seqB
    inj64<<<1024, 256>>>(0, wih_a1, bih_a1, bhh_a1);
    rec64<1><<<NPAIR, 256>>>(whh_a1, nullptr, nullptr, nullptr, nullptr, 1);
    // a2: inj from seqB -> prebuf; recurrence -> seqA
    inj64<<<1024, 256>>>(1, wih_a2, bih_a2, bhh_a2);
    rec64<1><<<NPAIR, 256>>>(whh_a2, nullptr, nullptr, nullptr, nullptr, 0);
    // b0 pre-gates from seqA
    preb0<<<512, 256>>>(wih_b0, bih_b0, bhh_b0);
    // b0/b1/b2 fused scalar recurrences -> out
    b012<<<8, 32>>>(whh_b0, wih_b1, whh_b1, bih_b1, bhh_b1,
                    wih_b2, whh_b2, bih_b2, bhh_b2, out);
}

// round 6
// speedup vs baseline: 2.2690x; 1.1047x over previous
#include <cuda_runtime.h>
#include <cstdint>

typedef unsigned long long u64;

#define B_    256
#define T_    512
#define NPAIR 128

// ---- device scratch (no allocations allowed) ------------------------------
__device__ __align__(16) float  g_seqA[(size_t)T_ * B_ * 64];   // 33.5 MB [t][b][64]
__device__ __align__(16) float4 g_pb0[(size_t)T_ * B_];         // 2 MB    [t*256+b]

// ---- packed f32x2 helpers -------------------------------------------------
__device__ __forceinline__ u64 pk2(float a, float b) {
    u64 r; asm("mov.b64 %0, {%1, %2};" : "=l"(r) : "f"(a), "f"(b)); return r;
}
__device__ __forceinline__ void unpk(u64 v, float& a, float& b) {
    asm("mov.b64 {%0, %1}, %2;" : "=f"(a), "=f"(b) : "l"(v));
}
__device__ __forceinline__ u64 ffma2(u64 a, u64 b, u64 c) {
    u64 d; asm("fma.rn.f32x2 %0, %1, %2, %3;" : "=l"(d) : "l"(a), "l"(b), "l"(c)); return d;
}
__device__ __forceinline__ u64 add2(u64 a, u64 b) {
    u64 d; asm("add.rn.f32x2 %0, %1, %2;" : "=l"(d) : "l"(a), "l"(b)); return d;
}
__device__ __forceinline__ float hsum2(u64 x, u64 y) {
    u64 s = add2(x, y);
    float e, o; unpk(s, e, o);
    return e + o;
}

// ---- fast activations (MUFU ex2+rcp, ~1e-7 err) ---------------------------
#define L2E 1.4426950408889634f
__device__ __forceinline__ float ex2a(float x) {
    float r; asm("ex2.approx.ftz.f32 %0, %1;" : "=f"(r) : "f"(x)); return r;
}
__device__ __forceinline__ float rcpa(float x) {
    float r; asm("rcp.approx.ftz.f32 %0, %1;" : "=f"(r) : "f"(x)); return r;
}
__device__ __forceinline__ float sga(float x) { return rcpa(1.f + ex2a(-L2E * x)); }
__device__ __forceinline__ float tna(float x) {
    return fmaf(-2.f, rcpa(1.f + ex2a(2.f * L2E * x)), 1.f);
}

// ---- fused a0+a1+a2 pipeline kernel ---------------------------------------
// 128 blocks (one batch pair), 256 threads (one gate each).
// Step s computes: a0 gates @t=s, a1 gates @t=s-1, a2 gates @t=s-2.
// Input projections for a1/a2 computed inline from smem h (no prebuf!).
// Weights: whh_a0, whh_a1 dim-packed in regs; wih_a1, wih_a2, whh_a2 in smem
// transposed to [chunk16B][gate] (coalesced warp loads).
//
// dynamic smem layout (bytes):
//   [0,       65536)  wT1 = wih_a1  as ulonglong2[16][256]
//   [65536,  131072)  wT2 = wih_a2
//   [131072, 196608)  wT3 = whh_a2
//   [196608, 200704)  xs  = float[2][512]
//   [200704, 206848)  gsm = float2[3][256]
//   [206848, 208384)  hs  = float[3][2][64]
#define SMEM_FUSE_BYTES 208384

__global__ __launch_bounds__(256, 1) void fuseA(
    const float* __restrict__ x,
    const float* __restrict__ wih_a0, const float* __restrict__ whh_a0,
    const float* __restrict__ bih_a0, const float* __restrict__ bhh_a0,
    const float* __restrict__ wih_a1, const float* __restrict__ whh_a1,
    const float* __restrict__ bih_a1, const float* __restrict__ bhh_a1,
    const float* __restrict__ wih_a2, const float* __restrict__ whh_a2,
    const float* __restrict__ bih_a2, const float* __restrict__ bhh_a2)
{
    extern __shared__ __align__(16) char smem[];
    ulonglong2* wT1 = reinterpret_cast<ulonglong2*>(smem);
    ulonglong2* wT2 = reinterpret_cast<ulonglong2*>(smem + 65536);
    ulonglong2* wT3 = reinterpret_cast<ulonglong2*>(smem + 131072);
    float*  xs  = reinterpret_cast<float*>(smem + 196608);   // [2][512]
    float2* gsm = reinterpret_cast<float2*>(smem + 200704);  // [3][256]
    float*  hs  = reinterpret_cast<float*>(smem + 206848);   // [3][2][64]

    const int g    = threadIdx.x;
    const int pair = blockIdx.x;

    // ---- register weight sets (dim-packed u64 rows: 32 u64 each) ----
    u64 wr0[32], wr1[32];
    {
        const u64* p0 = reinterpret_cast<const u64*>(whh_a0) + (size_t)g * 32;
        const u64* p1 = reinterpret_cast<const u64*>(whh_a1) + (size_t)g * 32;
#pragma unroll
        for (int j = 0; j < 32; ++j) { wr0[j] = __ldg(p0 + j); wr1[j] = __ldg(p1 + j); }
    }
    // ---- smem transposed weight sets: wT[i][g] = 16B chunk i of row g ----
    {
        const ulonglong2* p1 = reinterpret_cast<const ulonglong2*>(wih_a1) + (size_t)g * 16;
        const ulonglong2* p2 = reinterpret_cast<const ulonglong2*>(wih_a2) + (size_t)g * 16;
        const ulonglong2* p3 = reinterpret_cast<const ulonglong2*>(whh_a2) + (size_t)g * 16;
#pragma unroll
        for (int i = 0; i < 16; ++i) {
            wT1[i * 256 + g] = __ldg(p1 + i);
            wT2[i * 256 + g] = __ldg(p2 + i);
            wT3[i * 256 + g] = __ldg(p3 + i);
        }
    }
    // ---- x staging ----
#pragma unroll
    for (int k = 0; k < 4; ++k) {
        int i = g + 256 * k, bl = i >> 9, t = i & 511;
        xs[bl * 512 + t] = x[(size_t)(pair * 2 + bl) * T_ + t];
    }
    // ---- h init ----
    if (g < 128) {
#pragma unroll
        for (int L = 0; L < 3; ++L) hs[L * 128 + g] = 0.f;
    }

    const float bias0 = __ldg(bih_a0 + g) + __ldg(bhh_a0 + g);
    const float bias1 = __ldg(bih_a1 + g) + __ldg(bhh_a1 + g);
    const float bias2 = __ldg(bih_a2 + g) + __ldg(bhh_a2 + g);
    const float wx0   = __ldg(wih_a0 + g);

    const bool istanh = (g >= 128 && g < 192);
    const float ca = istanh ? 2.f * L2E : -L2E;
    const float aa = istanh ? 1.f : 0.f;
    const float bm = istanh ? -2.f : 1.f;

    float c0 = 0.f, c1 = 0.f, c2 = 0.f;
    __syncthreads();

#pragma unroll 1
    for (int s = 0; s < T_ + 2; ++s) {
        const bool L0 = (s < T_);
        const bool L1 = (s >= 1) & (s < T_ + 1);
        const bool L2 = (s >= 2);

        float v0a = 0.f, v0b = 0.f, p1a = 0.f, p1b = 0.f;
        float h1a = 0.f, h1b = 0.f, p2a = 0.f, p2b = 0.f;
        float h2a = 0.f, h2b = 0.f;

        // ---- group A: dots over h0 (whh_a0 regs + wih_a1 smem) ----
        if (L0 | L1) {
            const ulonglong2* q0p = reinterpret_cast<const ulonglong2*>(hs + 0);
            const ulonglong2* q1p = reinterpret_cast<const ulonglong2*>(hs + 64);
            u64 ax = 0, ay = 0, bx = 0, by = 0, ix = 0, iy = 0, jx = 0, jy = 0;
#pragma unroll
            for (int i = 0; i < 16; ++i) {
                ulonglong2 q0 = q0p[i], q1 = q1p[i];
                ulonglong2 wv = wT1[i * 256 + g];
                ax = ffma2(wr0[2 * i], q0.x, ax); ay = ffma2(wr0[2 * i + 1], q0.y, ay);
                bx = ffma2(wr0[2 * i], q1.x, bx); by = ffma2(wr0[2 * i + 1], q1.y, by);
                ix = ffma2(wv.x, q0.x, ix);       iy = ffma2(wv.y, q0.y, iy);
                jx = ffma2(wv.x, q1.x, jx);       jy = ffma2(wv.y, q1.y, jy);
            }
            v0a = hsum2(ax, ay); v0b = hsum2(bx, by);
            p1a = hsum2(ix, iy); p1b = hsum2(jx, jy);
        }
        // ---- group B: dots over h1 (whh_a1 regs + wih_a2 smem) ----
        if (L1 | L2) {
            const ulonglong2* q0p = reinterpret_cast<const ulonglong2*>(hs + 128);
            const ulonglong2* q1p = reinterpret_cast<const ulonglong2*>(hs + 192);
            u64 ax = 0, ay = 0, bx = 0, by = 0, ix = 0, iy = 0, jx = 0, jy = 0;
#pragma unroll
            for (int i = 0; i < 16; ++i) {
                ulonglong2 q0 = q0p[i], q1 = q1p[i];
                ulonglong2 wv = wT2[i * 256 + g];
                ax = ffma2(wr1[2 * i], q0.x, ax); ay = ffma2(wr1[2 * i + 1], q0.y, ay);
                bx = ffma2(wr1[2 * i], q1.x, bx); by = ffma2(wr1[2 * i + 1], q1.y, by);
                ix = ffma2(wv.x, q0.x, ix);       iy = ffma2(wv.y, q0.y, iy);
                jx = ffma2(wv.x, q1.x, jx);       jy = ffma2(wv.y, q1.y, jy);
            }
            h1a = hsum2(ax, ay); h1b = hsum2(bx, by);
            p2a = hsum2(ix, iy); p2b = hsum2(jx, jy);
        }
        // ---- group C: dot over h2 (whh_a2 smem) ----
        if (L2) {
            const ulonglong2* q0p = reinterpret_cast<const ulonglong2*>(hs + 256);
            const ulonglong2* q1p = reinterpret_cast<const ulonglong2*>(hs + 320);
            u64 ax = 0, ay = 0, bx = 0, by = 0;
#pragma unroll
            for (int i = 0; i < 16; ++i) {
                ulonglong2 q0 = q0p[i], q1 = q1p[i];
                ulonglong2 wv = wT3[i * 256 + g];
                ax = ffma2(wv.x, q0.x, ax); ay = ffma2(wv.y, q0.y, ay);
                bx = ffma2(wv.x, q1.x, bx); by = ffma2(wv.y, q1.y, by);
            }
            h2a = hsum2(ax, ay); h2b = hsum2(bx, by);
        }

        // ---- activations -> gsm ----
        if (L0) {
            float va = v0a + fmaf(wx0, xs[s], bias0);
            float vb = v0b + fmaf(wx0, xs[512 + s], bias0);
            gsm[g] = make_float2(fmaf(bm, rcpa(1.f + ex2a(ca * va)), aa),
                                 fmaf(bm, rcpa(1.f + ex2a(ca * vb)), aa));
        }
        if (L1) {
            float va = h1a + p1a + bias1;
            float vb = h1b + p1b + bias1;
            gsm[256 + g] = make_float2(fmaf(bm, rcpa(1.f + ex2a(ca * va)), aa),
                                       fmaf(bm, rcpa(1.f + ex2a(ca * vb)), aa));
        }
        if (L2) {
            float va = h2a + p2a + bias2;
            float vb = h2b + p2b + bias2;
            gsm[512 + g] = make_float2(fmaf(bm, rcpa(1.f + ex2a(ca * va)), aa),
                                       fmaf(bm, rcpa(1.f + ex2a(ca * vb)), aa));
        }
        __syncthreads();

        // ---- phase 2: c/h update (threads 0..127) ----
        if (g < 128) {
            const int u = g & 63, nb = g >> 6;
            if (L0) {
                float2 gi = gsm[u], gf = gsm[u + 64], gg = gsm[u + 128], go = gsm[u + 192];
                float iv = nb ? gi.y : gi.x, fv = nb ? gf.y : gf.x;
                float gv = nb ? gg.y : gg.x, ov = nb ? go.y : go.x;
                c0 = fmaf(fv, c0, iv * gv);
                hs[nb * 64 + u] = ov * tna(c0);
            }
            if (L1) {
                float2 gi = gsm[256 + u], gf = gsm[320 + u], gg = gsm[384 + u], go = gsm[448 + u];
                float iv = nb ? gi.y : gi.x, fv = nb ? gf.y : gf.x;
                float gv = nb ? gg.y : gg.x, ov = nb ? go.y : go.x;
                c1 = fmaf(fv, c1, iv * gv);
                hs[128 + nb * 64 + u] = ov * tna(c1);
            }
            if (L2) {
                float2 gi = gsm[512 + u], gf = gsm[576 + u], gg = gsm[640 + u], go = gsm[704 + u];
                float iv = nb ? gi.y : gi.x, fv = nb ? gf.y : gf.x;
                float gv = nb ? gg.y : gg.x, ov = nb ? go.y : go.x;
                c2 = fmaf(fv, c2, iv * gv);
                float h = ov * tna(c2);
                hs[256 + nb * 64 + u] = h;
                g_seqA[((size_t)(s - 2) * B_ + pair * 2 + nb) * 64 + u] = h;
            }
        }
        __syncthreads();
    }
}

// ---------------------------------------------------------------------------
// b0 pre-gates: g_pb0[t*256+b] = bias_b0 + W_ih_b0[4,64] . seqA[t][b]
// ---------------------------------------------------------------------------
__global__ __launch_bounds__(256, 1) void preb0(
    const float* __restrict__ w_ih, const float* __restrict__ b_ih,
    const float* __restrict__ b_hh)
{
    __shared__ u64 wsm[128];
    __shared__ float bsm[4];
    const int tid = threadIdx.x;
    if (tid < 128) wsm[tid] = __ldg(reinterpret_cast<const u64*>(w_ih) + tid);
    if (tid < 4) bsm[tid] = __ldg(b_ih + tid) + __ldg(b_hh + tid);
    __syncthreads();

    const size_t slot = (size_t)blockIdx.x * 256 + tid;  // = t*256 + b
    const u64* xp = reinterpret_cast<const u64*>(g_seqA) + slot * 32;
    u64 acc[4] = {0ull, 0ull, 0ull, 0ull};
#pragma unroll 8
    for (int j = 0; j < 32; ++j) {
        u64 xv = __ldg(xp + j);
#pragma unroll
        for (int gg = 0; gg < 4; ++gg)
            acc[gg] = ffma2(wsm[gg * 32 + j], xv, acc[gg]);
    }
    float r[4];
#pragma unroll
    for (int gg = 0; gg < 4; ++gg) {
        float e, o; unpk(acc[gg], e, o);
        r[gg] = e + o + bsm[gg];
    }
    g_pb0[slot] = make_float4(r[0], r[1], r[2], r[3]);
}

// ---------------------------------------------------------------------------
// b0,b1,b2 scalar recurrences, layer-pipelined. 8 blocks x 32 threads.
// ---------------------------------------------------------------------------
__device__ __forceinline__ void step1(float4 pre, float4 whh, float& c, float& h) {
    float iv = sga(fmaf(whh.x, h, pre.x));
    float fv = sga(fmaf(whh.y, h, pre.y));
    float gv = tna(fmaf(whh.z, h, pre.z));
    float ov = sga(fmaf(whh.w, h, pre.w));
    c = fmaf(fv, c, iv * gv);
    h = ov * tna(c);
}

__global__ __launch_bounds__(32, 1) void b012(
    const float* __restrict__ whh0,
    const float* __restrict__ wih1, const float* __restrict__ whh1,
    const float* __restrict__ bih1, const float* __restrict__ bhh1,
    const float* __restrict__ wih2, const float* __restrict__ whh2,
    const float* __restrict__ bih2, const float* __restrict__ bhh2,
    float* __restrict__ out)
{
    const int b = blockIdx.x * 32 + threadIdx.x;
    float4 W0 = make_float4(whh0[0], whh0[1], whh0[2], whh0[3]);
    float4 I1 = make_float4(wih1[0], wih1[1], wih1[2], wih1[3]);
    float4 H1 = make_float4(whh1[0], whh1[1], whh1[2], whh1[3]);
    float4 B1 = make_float4(bih1[0] + bhh1[0], bih1[1] + bhh1[1],
                            bih1[2] + bhh1[2], bih1[3] + bhh1[3]);
    float4 I2 = make_float4(wih2[0], wih2[1], wih2[2], wih2[3]);
    float4 H2 = make_float4(whh2[0], whh2[1], whh2[2], whh2[3]);
    float4 B2 = make_float4(bih2[0] + bhh2[0], bih2[1] + bhh2[1],
                            bih2[2] + bhh2[2], bih2[3] + bhh2[3]);

    float c0 = 0.f, h0 = 0.f, c1 = 0.f, h1 = 0.f, c2 = 0.f, h2v = 0.f;
    float4 p0 = g_pb0[b];
    float4 p1 = g_pb0[256 + b];

    for (int tt = 0; tt < T_ + 2; ++tt) {
        float4 pn = (tt + 2 < T_) ? g_pb0[(size_t)(tt + 2) * 256 + b]
                                  : make_float4(0.f, 0.f, 0.f, 0.f);
        float in0 = h0, in1 = h1;
        if (tt < T_) step1(p0, W0, c0, h0);
        if (tt >= 1 && tt < T_ + 1) {
            float4 pre = make_float4(fmaf(I1.x, in0, B1.x), fmaf(I1.y, in0, B1.y),
                                     fmaf(I1.z, in0, B1.z), fmaf(I1.w, in0, B1.w));
            step1(pre, H1, c1, h1);
        }
        if (tt >= 2) {
            float4 pre = make_float4(fmaf(I2.x, in1, B2.x), fmaf(I2.y, in1, B2.y),
                                     fmaf(I2.z, in1, B2.z), fmaf(I2.w, in1, B2.w));
            step1(pre, H2, c2, h2v);
            out[(size_t)b * T_ + (tt - 2)] = h2v;
        }
        p0 = p1; p1 = pn;
    }
}

// ---------------------------------------------------------------------------
extern "C" void kernel_launch(void* const* d_in, const int* in_sizes, int n_in,
                              void* d_out, int out_size)
{
    const float* x = (const float*)d_in[0];
    const float *wih_a0 = (const float*)d_in[1],  *whh_a0 = (const float*)d_in[2];
    const float *bih_a0 = (const float*)d_in[3],  *bhh_a0 = (const float*)d_in[4];
    const float *wih_a1 = (const float*)d_in[5],  *whh_a1 = (const float*)d_in[6];
    const float *bih_a1 = (const float*)d_in[7],  *bhh_a1 = (const float*)d_in[8];
    const float *wih_a2 = (const float*)d_in[9],  *whh_a2 = (const float*)d_in[10];
    const float *bih_a2 = (const float*)d_in[11], *bhh_a2 = (const float*)d_in[12];
    const float *wih_b0 = (const float*)d_in[13], *whh_b0 = (const float*)d_in[14];
    const float *bih_b0 = (const float*)d_in[15], *bhh_b0 = (const float*)d_in[16];
    const float *wih_b1 = (const float*)d_in[17], *whh_b1 = (const float*)d_in[18];
    const float *bih_b1 = (const float*)d_in[19], *bhh_b1 = (const float*)d_in[20];
    const float *wih_b2 = (const float*)d_in[21], *whh_b2 = (const float*)d_in[22];
    const float *bih_b2 = (const float*)d_in[23], *bhh_b2 = (const float*)d_in[24];
    float* out = (float*)d_out;

    static int smem_set = 0;
    if (!smem_set) {
        cudaFuncSetAttribute(fuseA, cudaFuncAttributeMaxDynamicSharedMemorySize,
                             SMEM_FUSE_BYTES);
        smem_set = 1;
    }

    // fused a0+a1+a2 pipeline -> g_seqA
    fuseA<<<NPAIR, 256, SMEM_FUSE_BYTES>>>(
        x,
        wih_a0, whh_a0, bih_a0, bhh_a0,
        wih_a1, whh_a1, bih_a1, bhh_a1,
        wih_a2, whh_a2, bih_a2, bhh_a2);
    // b0 pre-gates from g_seqA
    preb0<<<512, 256>>>(wih_b0, bih_b0, bhh_b0);
    // b0/b1/b2 fused scalar recurrences -> out
    b012<<<8, 32>>>(whh_b0, wih_b1, whh_b1, bih_b1, bhh_b1,
                    wih_b2, whh_b2, bih_b2, bhh_b2, out);
}